// round 8
// baseline (speedup 1.0000x reference)
#include <cuda_runtime.h>

#define D 64
#define KC 400
#define MTILE 128
#define NTILE 128
#define TPB 128
#define TS 132            // tile stride (floats); [d][.] tiles, swizzled
#define NFULL 3
#define KTAIL 16

// smem byte offsets
#define OFF_XS 0                  // float[64*TS]
#define OFF_ES 33792              // float[64*TS]
#define OFF_N2 67584              // float[128]
#define OFF_RW 68096              // int[128]
#define SMEM_BYTES 68608
// reduction overlays es
#define OFF_SB OFF_ES             // float[128*11]
#define OFF_SI (OFF_ES + 5632)    // int[128*11]

#define SWZ(d) ((((d) >> 2) & 7) << 2)   // XOR on row bits 2-4: preserves float4 alignment

__device__ __forceinline__ void fma2(unsigned long long &acc, unsigned long long a,
                                     unsigned long long b) {
    asm("fma.rn.f32x2 %0, %1, %2, %0;" : "+l"(acc) : "l"(a), "l"(b));
}
__device__ __forceinline__ void unpack2(unsigned long long v, float &lo, float &hi) {
    asm("mov.b64 {%0, %1}, %2;" : "=f"(lo), "=f"(hi) : "l"(v));
}
__device__ __forceinline__ unsigned long long pack2(float lo, float hi) {
    unsigned long long r;
    asm("mov.b64 %0, {%1, %2};" : "=l"(r) : "f"(lo), "f"(hi));
    return r;
}

__global__ void __launch_bounds__(TPB, 3)
vq_tiled_kernel(const float* __restrict__ x, const float* __restrict__ emb,
                float* __restrict__ out, int nrows) {
    extern __shared__ char sm[];
    float* xs  = (float*)(sm + OFF_XS);
    float* es  = (float*)(sm + OFF_ES);
    float* n2c = (float*)(sm + OFF_N2);
    int*   rw  = (int*)(sm + OFF_RW);

    const int tid = threadIdx.x;
    const int tx = tid & 7;         // 8 code groups of 16
    const int ty = tid >> 3;        // 16 row groups of 8
    const int row0 = blockIdx.x * MTILE;

    const float4* xg = (const float4*)(x + (size_t)row0 * D);
    const float4* eg = (const float4*)emb;

    // ---- stage x: coalesced LDG (512B/warp), swizzled transposed STS ----
    for (int i = tid; i < MTILE * 16; i += TPB) {
        int db = i & 15, row = i >> 4;
        float4 v = xg[row * 16 + db];
        int sw = (db & 7) << 2;                  // == SWZ(4*db+c), c-independent
        xs[(4 * db + 0) * TS + (row ^ sw)] = v.x;
        xs[(4 * db + 1) * TS + (row ^ sw)] = v.y;
        xs[(4 * db + 2) * TS + (row ^ sw)] = v.z;
        xs[(4 * db + 3) * TS + (row ^ sw)] = v.w;
    }

    unsigned long long acc[64];     // [m(8)][np(8)] packed pairs: 8 rows x 16 codes
    float bst[8];
    int   bidx[8];
    #pragma unroll
    for (int m = 0; m < 8; m++) { bst[m] = -3.4e38f; bidx[m] = 0; }

    for (int c = 0; c < NFULL; c++) {
        const int g0 = c * NTILE;
        __syncthreads();

        // ---- stage e chunk: coalesced LDG, swizzled STS ----
        for (int i = tid; i < NTILE * 16; i += TPB) {
            int db = i & 15, code = i >> 4;
            float4 v = eg[(size_t)(g0 + code) * 16 + db];
            int sw = (db & 7) << 2;
            es[(4 * db + 0) * TS + (code ^ sw)] = v.x;
            es[(4 * db + 1) * TS + (code ^ sw)] = v.y;
            es[(4 * db + 2) * TS + (code ^ sw)] = v.z;
            es[(4 * db + 3) * TS + (code ^ sw)] = v.w;
        }
        __syncthreads();

        // ---- -0.5||e||^2 per code ----
        if (tid < NTILE) {
            float s = 0.f;
            #pragma unroll 16
            for (int d = 0; d < D; d++) {
                float e = es[d * TS + (tid ^ SWZ(d))];
                s = fmaf(e, e, s);
            }
            n2c[tid] = -0.5f * s;
        }
        __syncthreads();

        // ---- init accs with folded norms ----
        #pragma unroll
        for (int np = 0; np < 8; np++) {
            unsigned long long n2 = *(const unsigned long long*)(n2c + tx * 16 + np * 2);
            #pragma unroll
            for (int m = 0; m < 8; m++) acc[m * 8 + np] = n2;
        }

        // ---- MMA over d: 8 x-floats + 16 e-floats -> 128 FFMA2 per d ----
        #pragma unroll 2
        for (int d = 0; d < D; d++) {
            const int sw = SWZ(d);
            const float* xr = xs + d * TS;
            const float* er = es + d * TS;
            float4 xa = *(const float4*)(xr + ((ty * 8) ^ sw));
            float4 xb = *(const float4*)(xr + ((ty * 8 + 4) ^ sw));
            ulonglong2 e0 = *(const ulonglong2*)(er + ((tx * 16) ^ sw));
            ulonglong2 e1 = *(const ulonglong2*)(er + ((tx * 16 + 4) ^ sw));
            ulonglong2 e2 = *(const ulonglong2*)(er + ((tx * 16 + 8) ^ sw));
            ulonglong2 e3 = *(const ulonglong2*)(er + ((tx * 16 + 12) ^ sw));
            unsigned long long ep[8] = {e0.x, e0.y, e1.x, e1.y, e2.x, e2.y, e3.x, e3.y};
            float xm[8] = {xa.x, xa.y, xa.z, xa.w, xb.x, xb.y, xb.z, xb.w};
            #pragma unroll
            for (int m = 0; m < 8; m++) {
                unsigned long long xp = pack2(xm[m], xm[m]);
                #pragma unroll
                for (int np = 0; np < 8; np++) fma2(acc[m * 8 + np], xp, ep[np]);
            }
        }

        // ---- epilogue: strict > ascending index == jnp first-min ----
        #pragma unroll
        for (int m = 0; m < 8; m++) {
            #pragma unroll
            for (int np = 0; np < 8; np++) {
                float lo, hi;
                unpack2(acc[m * 8 + np], lo, hi);
                int n = g0 + tx * 16 + np * 2;
                if (lo > bst[m]) { bst[m] = lo; bidx[m] = n; }
                if (hi > bst[m]) { bst[m] = hi; bidx[m] = n + 1; }
            }
        }
    }

    // ================= tail: codes 384..399 =================
    __syncthreads();
    for (int i = tid; i < KTAIL * 16; i += TPB) {
        int db = i & 15, code = i >> 4;
        float4 v = eg[(size_t)(NFULL * NTILE + code) * 16 + db];
        int sw = (db & 7) << 2;
        es[(4 * db + 0) * TS + (code ^ sw)] = v.x;
        es[(4 * db + 1) * TS + (code ^ sw)] = v.y;
        es[(4 * db + 2) * TS + (code ^ sw)] = v.z;
        es[(4 * db + 3) * TS + (code ^ sw)] = v.w;
    }
    __syncthreads();
    if (tid < KTAIL) {
        float s = 0.f;
        #pragma unroll 16
        for (int d = 0; d < D; d++) {
            float e = es[d * TS + (tid ^ SWZ(d))];
            s = fmaf(e, e, s);
        }
        n2c[tid] = -0.5f * s;
    }
    __syncthreads();

    // tail: 2 rows x 8 codes per thread
    float tb0, tb1;
    int   ti0, ti1;
    {
        const int tx2 = tid & 1;
        const int ry  = tid >> 1;            // rows ry*2, ry*2+1
        unsigned long long a0[4], a1[4];
        #pragma unroll
        for (int np = 0; np < 4; np++) {
            unsigned long long n2 = *(const unsigned long long*)(n2c + tx2 * 8 + np * 2);
            a0[np] = n2; a1[np] = n2;
        }
        #pragma unroll 4
        for (int d = 0; d < D; d++) {
            const int sw = SWZ(d);
            const float* xr = xs + d * TS;
            const float* er = es + d * TS;
            float2 xv = *(const float2*)(xr + ((ry * 2) ^ sw));
            ulonglong2 ea = *(const ulonglong2*)(er + ((tx2 * 8) ^ sw));
            ulonglong2 eb = *(const ulonglong2*)(er + ((tx2 * 8 + 4) ^ sw));
            unsigned long long xp0 = pack2(xv.x, xv.x);
            unsigned long long xp1 = pack2(xv.y, xv.y);
            fma2(a0[0], xp0, ea.x); fma2(a0[1], xp0, ea.y);
            fma2(a0[2], xp0, eb.x); fma2(a0[3], xp0, eb.y);
            fma2(a1[0], xp1, ea.x); fma2(a1[1], xp1, ea.y);
            fma2(a1[2], xp1, eb.x); fma2(a1[3], xp1, eb.y);
        }
        tb0 = -3.4e38f; ti0 = 0; tb1 = -3.4e38f; ti1 = 0;
        #pragma unroll
        for (int np = 0; np < 4; np++) {
            float lo, hi;
            int n = NFULL * NTILE + tx2 * 8 + np * 2;
            unpack2(a0[np], lo, hi);
            if (lo > tb0) { tb0 = lo; ti0 = n; }
            if (hi > tb0) { tb0 = hi; ti0 = n + 1; }
            unpack2(a1[np], lo, hi);
            if (lo > tb1) { tb1 = lo; ti1 = n; }
            if (hi > tb1) { tb1 = hi; ti1 = n + 1; }
        }
    }

    // ---- cross-thread reduction: 8 main + 2 tail candidates per row ----
    __syncthreads();                       // es readers done; overlay sb/si
    float* sb = (float*)(sm + OFF_SB);     // [128][11]
    int*   si = (int*)(sm + OFF_SI);       // [128][11]
    #pragma unroll
    for (int m = 0; m < 8; m++) {
        int row = ty * 8 + m;
        sb[row * 11 + tx] = bst[m];
        si[row * 11 + tx] = bidx[m];
    }
    {
        int ry = tid >> 1, slot = 8 + (tid & 1);
        sb[(ry * 2) * 11 + slot]     = tb0;
        si[(ry * 2) * 11 + slot]     = ti0;
        sb[(ry * 2 + 1) * 11 + slot] = tb1;
        si[(ry * 2 + 1) * 11 + slot] = ti1;
    }
    __syncthreads();
    if (tid < MTILE) {
        float b = -3.4e38f;
        int bi = 0;
        #pragma unroll
        for (int t = 0; t < 10; t++) {
            float s = sb[tid * 11 + t];
            int   i = si[tid * 11 + t];
            if (s > b || (s == b && i < bi)) { b = s; bi = i; }
        }
        rw[tid] = bi;
    }
    __syncthreads();

    // ---- gather winning codes (L2-hot), write out ----
    float4* og = (float4*)(out + (size_t)row0 * D);
    for (int i = tid; i < MTILE * 16; i += TPB) {
        int r = i >> 4, q = i & 15;
        og[r * 16 + q] = eg[(size_t)rw[r] * 16 + q];
    }
}

extern "C" void kernel_launch(void* const* d_in, const int* in_sizes, int n_in,
                              void* d_out, int out_size) {
    const float* x   = (const float*)d_in[0];
    const float* emb = (const float*)d_in[1];
    float* out = (float*)d_out;

    int nrows = in_sizes[0] / D;   // 262144, divisible by MTILE

    cudaFuncSetAttribute(vq_tiled_kernel,
                         cudaFuncAttributeMaxDynamicSharedMemorySize, SMEM_BYTES);

    int blocks = nrows / MTILE;    // 2048
    vq_tiled_kernel<<<blocks, TPB, SMEM_BYTES>>>(x, emb, out, nrows);
}

// round 9
// speedup vs baseline: 1.6232x; 1.6232x over previous
#include <cuda_runtime.h>

#define D 64
#define KC 400
#define MTILE 128
#define NTILE 128
#define TPB 128
#define TS 132            // tile stride (floats); [d][.] tiles, swizzled
#define NFULL 3
#define KTAIL 16

// smem byte offsets
#define OFF_XS 0                  // float[64*TS]
#define OFF_ES 33792              // float[64*TS]
#define OFF_N2 67584              // float[128]
#define OFF_RW 68096              // int[128]
#define SMEM_BYTES 68608
// reduction overlays es
#define OFF_SB OFF_ES             // float[128*11]
#define OFF_SI (OFF_ES + 5632)    // int[128*11]

#define SWZ(d) ((((d) >> 2) & 7) << 2)   // XOR on row bits 2-4: float4-alignment preserving

__device__ __forceinline__ void fma2(unsigned long long &acc, unsigned long long a,
                                     unsigned long long b) {
    asm("fma.rn.f32x2 %0, %1, %2, %0;" : "+l"(acc) : "l"(a), "l"(b));
}
__device__ __forceinline__ void unpack2(unsigned long long v, float &lo, float &hi) {
    asm("mov.b64 {%0, %1}, %2;" : "=f"(lo), "=f"(hi) : "l"(v));
}
__device__ __forceinline__ unsigned long long pack2(float lo, float hi) {
    unsigned long long r;
    asm("mov.b64 %0, {%1, %2};" : "=l"(r) : "f"(lo), "f"(hi));
    return r;
}

__global__ void __launch_bounds__(TPB, 2)   // 2 CTAs: 255-reg cap -> 128 accs fit, NO spill
vq_tiled_kernel(const float* __restrict__ x, const float* __restrict__ emb,
                float* __restrict__ out, int nrows) {
    extern __shared__ char sm[];
    float* xs  = (float*)(sm + OFF_XS);
    float* es  = (float*)(sm + OFF_ES);
    float* n2c = (float*)(sm + OFF_N2);
    int*   rw  = (int*)(sm + OFF_RW);

    const int tid = threadIdx.x;
    const int tx = tid & 7;         // 8 code groups of 16
    const int ty = tid >> 3;        // 16 row groups of 8
    const int row0 = blockIdx.x * MTILE;

    const float4* xg = (const float4*)(x + (size_t)row0 * D);
    const float4* eg = (const float4*)emb;

    // ---- stage x: coalesced LDG (512B/warp), swizzled transposed STS ----
    for (int i = tid; i < MTILE * 16; i += TPB) {
        int db = i & 15, row = i >> 4;
        float4 v = xg[row * 16 + db];
        int sw = (db & 7) << 2;                  // == SWZ(4*db+c), c-independent
        xs[(4 * db + 0) * TS + (row ^ sw)] = v.x;
        xs[(4 * db + 1) * TS + (row ^ sw)] = v.y;
        xs[(4 * db + 2) * TS + (row ^ sw)] = v.z;
        xs[(4 * db + 3) * TS + (row ^ sw)] = v.w;
    }

    unsigned long long acc[64];     // [m(8)][np(8)]: 8 rows x 16 codes
    float bst[8];
    int   bidx[8];
    #pragma unroll
    for (int m = 0; m < 8; m++) { bst[m] = -3.4e38f; bidx[m] = 0; }

    for (int c = 0; c < NFULL; c++) {
        const int g0 = c * NTILE;
        __syncthreads();

        // ---- stage e chunk: coalesced LDG, swizzled STS ----
        for (int i = tid; i < NTILE * 16; i += TPB) {
            int db = i & 15, code = i >> 4;
            float4 v = eg[(size_t)(g0 + code) * 16 + db];
            int sw = (db & 7) << 2;
            es[(4 * db + 0) * TS + (code ^ sw)] = v.x;
            es[(4 * db + 1) * TS + (code ^ sw)] = v.y;
            es[(4 * db + 2) * TS + (code ^ sw)] = v.z;
            es[(4 * db + 3) * TS + (code ^ sw)] = v.w;
        }
        __syncthreads();

        // ---- -0.5||e||^2 per code ----
        if (tid < NTILE) {
            float s = 0.f;
            #pragma unroll 16
            for (int d = 0; d < D; d++) {
                float e = es[d * TS + (tid ^ SWZ(d))];
                s = fmaf(e, e, s);
            }
            n2c[tid] = -0.5f * s;
        }
        __syncthreads();

        // ---- init accs with folded norms ----
        #pragma unroll
        for (int np = 0; np < 8; np++) {
            unsigned long long n2 = *(const unsigned long long*)(n2c + tx * 16 + np * 2);
            #pragma unroll
            for (int m = 0; m < 8; m++) acc[m * 8 + np] = n2;
        }

        // ---- MMA over d: 8 x + 16 e floats -> 128 MACs (64 FFMA2) per d ----
        #pragma unroll 2
        for (int d = 0; d < D; d++) {
            const int sw = SWZ(d);
            const float* xr = xs + d * TS;
            const float* er = es + d * TS;
            float4 xa = *(const float4*)(xr + ((ty * 8) ^ sw));
            float4 xb = *(const float4*)(xr + ((ty * 8 + 4) ^ sw));
            ulonglong2 e0 = *(const ulonglong2*)(er + ((tx * 16) ^ sw));
            ulonglong2 e1 = *(const ulonglong2*)(er + ((tx * 16 + 4) ^ sw));
            ulonglong2 e2 = *(const ulonglong2*)(er + ((tx * 16 + 8) ^ sw));
            ulonglong2 e3 = *(const ulonglong2*)(er + ((tx * 16 + 12) ^ sw));
            unsigned long long ep[8] = {e0.x, e0.y, e1.x, e1.y, e2.x, e2.y, e3.x, e3.y};
            float xm[8] = {xa.x, xa.y, xa.z, xa.w, xb.x, xb.y, xb.z, xb.w};
            #pragma unroll
            for (int m = 0; m < 8; m++) {
                unsigned long long xp = pack2(xm[m], xm[m]);
                #pragma unroll
                for (int np = 0; np < 8; np++) fma2(acc[m * 8 + np], xp, ep[np]);
            }
        }

        // ---- epilogue: strict > ascending index == jnp first-min ----
        #pragma unroll
        for (int m = 0; m < 8; m++) {
            #pragma unroll
            for (int np = 0; np < 8; np++) {
                float lo, hi;
                unpack2(acc[m * 8 + np], lo, hi);
                int n = g0 + tx * 16 + np * 2;
                if (lo > bst[m]) { bst[m] = lo; bidx[m] = n; }
                if (hi > bst[m]) { bst[m] = hi; bidx[m] = n + 1; }
            }
        }
    }

    // ================= tail: codes 384..399 =================
    __syncthreads();
    for (int i = tid; i < KTAIL * 16; i += TPB) {
        int db = i & 15, code = i >> 4;
        float4 v = eg[(size_t)(NFULL * NTILE + code) * 16 + db];
        int sw = (db & 7) << 2;
        es[(4 * db + 0) * TS + (code ^ sw)] = v.x;
        es[(4 * db + 1) * TS + (code ^ sw)] = v.y;
        es[(4 * db + 2) * TS + (code ^ sw)] = v.z;
        es[(4 * db + 3) * TS + (code ^ sw)] = v.w;
    }
    __syncthreads();
    if (tid < KTAIL) {
        float s = 0.f;
        #pragma unroll 16
        for (int d = 0; d < D; d++) {
            float e = es[d * TS + (tid ^ SWZ(d))];
            s = fmaf(e, e, s);
        }
        n2c[tid] = -0.5f * s;
    }
    __syncthreads();

    // tail: 2 rows x 8 codes per thread (128 threads cover 128 rows x 16 codes)
    float tb0, tb1;
    int   ti0, ti1;
    {
        const int tx2 = tid & 1;
        const int ry  = tid >> 1;            // rows ry*2, ry*2+1
        unsigned long long a0[4], a1[4];
        #pragma unroll
        for (int np = 0; np < 4; np++) {
            unsigned long long n2 = *(const unsigned long long*)(n2c + tx2 * 8 + np * 2);
            a0[np] = n2; a1[np] = n2;
        }
        #pragma unroll 4
        for (int d = 0; d < D; d++) {
            const int sw = SWZ(d);
            const float* xr = xs + d * TS;
            const float* er = es + d * TS;
            float2 xv = *(const float2*)(xr + ((ry * 2) ^ sw));
            ulonglong2 ea = *(const ulonglong2*)(er + ((tx2 * 8) ^ sw));
            ulonglong2 eb = *(const ulonglong2*)(er + ((tx2 * 8 + 4) ^ sw));
            unsigned long long xp0 = pack2(xv.x, xv.x);
            unsigned long long xp1 = pack2(xv.y, xv.y);
            fma2(a0[0], xp0, ea.x); fma2(a0[1], xp0, ea.y);
            fma2(a0[2], xp0, eb.x); fma2(a0[3], xp0, eb.y);
            fma2(a1[0], xp1, ea.x); fma2(a1[1], xp1, ea.y);
            fma2(a1[2], xp1, eb.x); fma2(a1[3], xp1, eb.y);
        }
        tb0 = -3.4e38f; ti0 = 0; tb1 = -3.4e38f; ti1 = 0;
        #pragma unroll
        for (int np = 0; np < 4; np++) {
            float lo, hi;
            int n = NFULL * NTILE + tx2 * 8 + np * 2;
            unpack2(a0[np], lo, hi);
            if (lo > tb0) { tb0 = lo; ti0 = n; }
            if (hi > tb0) { tb0 = hi; ti0 = n + 1; }
            unpack2(a1[np], lo, hi);
            if (lo > tb1) { tb1 = lo; ti1 = n; }
            if (hi > tb1) { tb1 = hi; ti1 = n + 1; }
        }
    }

    // ---- cross-thread reduction: 8 main + 2 tail candidates per row ----
    __syncthreads();                       // es readers done; overlay sb/si
    float* sb = (float*)(sm + OFF_SB);     // [128][11]
    int*   si = (int*)(sm + OFF_SI);       // [128][11]
    #pragma unroll
    for (int m = 0; m < 8; m++) {
        int row = ty * 8 + m;
        sb[row * 11 + tx] = bst[m];
        si[row * 11 + tx] = bidx[m];
    }
    {
        int ry = tid >> 1, slot = 8 + (tid & 1);
        sb[(ry * 2) * 11 + slot]     = tb0;
        si[(ry * 2) * 11 + slot]     = ti0;
        sb[(ry * 2 + 1) * 11 + slot] = tb1;
        si[(ry * 2 + 1) * 11 + slot] = ti1;
    }
    __syncthreads();
    if (tid < MTILE) {
        float b = -3.4e38f;
        int bi = 0;
        #pragma unroll
        for (int t = 0; t < 10; t++) {
            float s = sb[tid * 11 + t];
            int   i = si[tid * 11 + t];
            if (s > b || (s == b && i < bi)) { b = s; bi = i; }
        }
        rw[tid] = bi;
    }
    __syncthreads();

    // ---- gather winning codes (L2-hot), write out ----
    float4* og = (float4*)(out + (size_t)row0 * D);
    for (int i = tid; i < MTILE * 16; i += TPB) {
        int r = i >> 4, q = i & 15;
        og[r * 16 + q] = eg[(size_t)rw[r] * 16 + q];
    }
}

extern "C" void kernel_launch(void* const* d_in, const int* in_sizes, int n_in,
                              void* d_out, int out_size) {
    const float* x   = (const float*)d_in[0];
    const float* emb = (const float*)d_in[1];
    float* out = (float*)d_out;

    int nrows = in_sizes[0] / D;   // 262144, divisible by MTILE

    cudaFuncSetAttribute(vq_tiled_kernel,
                         cudaFuncAttributeMaxDynamicSharedMemorySize, SMEM_BYTES);

    int blocks = nrows / MTILE;    // 2048
    vq_tiled_kernel<<<blocks, TPB, SMEM_BYTES>>>(x, emb, out, nrows);
}